// round 5
// baseline (speedup 1.0000x reference)
#include <cuda_runtime.h>
#include <string.h>

#define BATCH 128
#define TLEN  8192
#define HDIM  96
#define NTHR  832   // 2 groups x (12 gate warps + 1 output warp)

// Packed fp32x2 FMA (Blackwell).
#define FMA2(d, a, b, c) \
    asm("fma.rn.f32x2 %0, %1, %2, %3;" : "=l"(d) : "l"(a), "l"(b), "l"(c))
#define ADD2(d, a, b) \
    asm("add.rn.f32x2 %0, %1, %2;" : "=l"(d) : "l"(a), "l"(b))
#define UNPACK2(lo, hi, v) \
    asm("mov.b64 {%0, %1}, %2;" : "=f"(lo), "=f"(hi) : "l"(v))

__device__ __forceinline__ float ex2_fast(float x) {
    float y; asm("ex2.approx.f32 %0, %1;" : "=f"(y) : "f"(x)); return y;
}
__device__ __forceinline__ float rcp_fast(float x) {
    float y; asm("rcp.approx.f32 %0, %1;" : "=f"(y) : "f"(x)); return y;
}
// group-scoped named barrier (416 threads each, ids 1 and 2)
__device__ __forceinline__ void group_bar(int id) {
    asm volatile("bar.sync %0, %1;" :: "r"(id), "r"(416) : "memory");
}

#define LOG2E 1.4426950408889634f

__global__ void __launch_bounds__(NTHR, 1)
lstm_persistent_kernel(const float* __restrict__ x,
                       const float* __restrict__ w_ih,
                       const float* __restrict__ w_hh,
                       const float* __restrict__ b_ih,
                       const float* __restrict__ b_hh,
                       const float* __restrict__ w_out,
                       const float* __restrict__ b_out,
                       float* __restrict__ out)
{
    __shared__ __align__(16) float h_s[2][2][HDIM];   // [elem][phase][H]

    const int tid  = threadIdx.x;
    const int wid  = tid >> 5;
    const int lane = tid & 31;

    int elem, gwid;
    bool is_gate;
    if (wid < 24) { elem = wid >= 12; gwid = wid - 12 * elem; is_gate = true; }
    else          { elem = wid - 24; gwid = 0;               is_gate = false; }

    const int b = blockIdx.x * 2 + elem;
    const float* xrow   = x   + (size_t)b * TLEN;
    float*       outrow = out + (size_t)b * TLEN;

    if (tid < 2 * 2 * HDIM) ((float*)h_s)[tid] = 0.0f;

    const int u = 8 * gwid + (lane >> 2);  // hidden unit 0..95
    const int q = lane & 3;                // h-quarter in matvec; gate id after butterfly

    // Per-lane weights: rows of all 4 gates for unit u, columns [24q, 24q+24),
    // prescaled by log2e * (2 for tanh-gate) so activations use raw ex2.
    ulonglong2 wreg[4][6];
    float wi = 0.0f, bias = 0.0f;
    if (is_gate) {
        #pragma unroll
        for (int g = 0; g < 4; g++) {
            const float sg = (g == 2) ? 2.0f * LOG2E : LOG2E;
            const float4* wr = (const float4*)(w_hh + (size_t)(g * HDIM + u) * HDIM + 24 * q);
            #pragma unroll
            for (int j = 0; j < 6; j++) {
                float4 t = wr[j];
                t.x *= sg; t.y *= sg; t.z *= sg; t.w *= sg;
                ulonglong2 pk;
                memcpy(&pk, &t, 16);
                wreg[g][j] = pk;
            }
        }
        const float sq = (q == 2) ? 2.0f * LOG2E : LOG2E;
        const int row = q * HDIM + u;
        wi   = w_ih[row] * sq;
        bias = (b_ih[row] + b_hh[row]) * sq;
    }
    const float mq = (q == 2) ? 2.0f : 1.0f;   // act = 1 - mq*rcp(ex2(z)+1)
    const int  base = lane & ~3;
    const int  b0 = lane & 1, b1 = lane & 2;

    // Output warp setup
    float wo0 = 0.f, wo1 = 0.f, wo2 = 0.f, bo = 0.f;
    if (!is_gate) {
        wo0 = w_out[lane];
        wo1 = w_out[lane + 32];
        wo2 = w_out[lane + 64];
        bo  = b_out[0];
    }

    float c = 0.0f;                          // cell state (q==0 lanes)
    const int barid = elem + 1;

    __syncthreads();                         // weights + h init visible

    int p = 0;
    float xt = __ldg(xrow);                  // prefetched input sample
    for (int t = 0; t < TLEN; t++) {
        if (is_gate) {
            // ---- matvec: each lane does all 4 gates over its h-quarter ----
            const ulonglong2* hq = (const ulonglong2*)(h_s[elem][p] + 24 * q);
            ulonglong2 h0 = hq[0], h1 = hq[1], h2v = hq[2];
            ulonglong2 h3 = hq[3], h4 = hq[4], h5 = hq[5];
            float pre = fmaf(xt, wi, bias);
            if (t + 1 < TLEN) xt = __ldg(xrow + t + 1);   // off the critical chain

            unsigned long long acc[4][2];
            #pragma unroll
            for (int g = 0; g < 4; g++) { acc[g][0] = 0ull; acc[g][1] = 0ull; }
            #pragma unroll
            for (int g = 0; g < 4; g++) {
                FMA2(acc[g][0], wreg[g][0].x, h0.x, acc[g][0]);
                FMA2(acc[g][1], wreg[g][0].y, h0.y, acc[g][1]);
                FMA2(acc[g][0], wreg[g][1].x, h1.x, acc[g][0]);
                FMA2(acc[g][1], wreg[g][1].y, h1.y, acc[g][1]);
                FMA2(acc[g][0], wreg[g][2].x, h2v.x, acc[g][0]);
                FMA2(acc[g][1], wreg[g][2].y, h2v.y, acc[g][1]);
                FMA2(acc[g][0], wreg[g][3].x, h3.x, acc[g][0]);
                FMA2(acc[g][1], wreg[g][3].y, h3.y, acc[g][1]);
                FMA2(acc[g][0], wreg[g][4].x, h4.x, acc[g][0]);
                FMA2(acc[g][1], wreg[g][4].y, h4.y, acc[g][1]);
                FMA2(acc[g][0], wreg[g][5].x, h5.x, acc[g][0]);
                FMA2(acc[g][1], wreg[g][5].y, h5.y, acc[g][1]);
            }
            float pg[4];
            #pragma unroll
            for (int g = 0; g < 4; g++) {
                unsigned long long s;
                ADD2(s, acc[g][0], acc[g][1]);
                float lo, hi;
                UNPACK2(lo, hi, s);
                pg[g] = lo + hi;
            }

            // ---- butterfly: lane q ends with gate q's full sum ----
            float keepA = b0 ? pg[1] : pg[0];
            float sendA = b0 ? pg[0] : pg[1];
            float keepB = b0 ? pg[3] : pg[2];
            float sendB = b0 ? pg[2] : pg[3];
            keepA += __shfl_xor_sync(0xffffffffu, sendA, 1);
            keepB += __shfl_xor_sync(0xffffffffu, sendB, 1);
            float keep = b1 ? keepB : keepA;
            float send = b1 ? keepA : keepB;
            float z = keep + __shfl_xor_sync(0xffffffffu, send, 2) + pre;

            // branchless activation in log2 domain: 1 - mq/(2^z + 1)
            float e   = ex2_fast(z);
            float r   = rcp_fast(e + 1.0f);
            float act = fmaf(-mq, r, 1.0f);

            // gather f, g, o into the q==0 lane
            float fv = __shfl_sync(0xffffffffu, act, base + 1);
            float gv = __shfl_sync(0xffffffffu, act, base + 2);
            float ov = __shfl_sync(0xffffffffu, act, base + 3);

            if (q == 0) {   // c/h update distributed across the 12 warps
                c = fmaf(fv, c, act * gv);
                float e2 = ex2_fast(c * (2.0f * LOG2E));
                float tc = fmaf(-2.0f, rcp_fast(e2 + 1.0f), 1.0f);
                h_s[elem][p ^ 1][u] = ov * tc;
            }
        } else {
            // ---- output warp: emit y(t-1) from h(t-1), hidden under the matvec ----
            if (t > 0) {
                float part = h_s[elem][p][lane] * wo0 + h_s[elem][p][lane + 32] * wo1
                           + h_s[elem][p][lane + 64] * wo2;
                part += __shfl_xor_sync(0xffffffffu, part, 16);
                part += __shfl_xor_sync(0xffffffffu, part, 8);
                part += __shfl_xor_sync(0xffffffffu, part, 4);
                part += __shfl_xor_sync(0xffffffffu, part, 2);
                part += __shfl_xor_sync(0xffffffffu, part, 1);
                if (lane == 0) outrow[t - 1] = part + bo;
            }
        }
        group_bar(barid);   // group-private barrier: two elements stay decoupled
        p ^= 1;
    }

    // final output y(T-1)
    if (!is_gate) {
        float part = h_s[elem][p][lane] * wo0 + h_s[elem][p][lane + 32] * wo1
                   + h_s[elem][p][lane + 64] * wo2;
        part += __shfl_xor_sync(0xffffffffu, part, 16);
        part += __shfl_xor_sync(0xffffffffu, part, 8);
        part += __shfl_xor_sync(0xffffffffu, part, 4);
        part += __shfl_xor_sync(0xffffffffu, part, 2);
        part += __shfl_xor_sync(0xffffffffu, part, 1);
        if (lane == 0) outrow[TLEN - 1] = part + bo;
    }
}

extern "C" void kernel_launch(void* const* d_in, const int* in_sizes, int n_in,
                              void* d_out, int out_size)
{
    const float* x     = (const float*)d_in[0];
    const float* w_ih  = (const float*)d_in[1];
    const float* w_hh  = (const float*)d_in[2];
    const float* b_ih  = (const float*)d_in[3];
    const float* b_hh  = (const float*)d_in[4];
    const float* w_out = (const float*)d_in[5];
    const float* b_out = (const float*)d_in[6];
    float* out = (float*)d_out;

    lstm_persistent_kernel<<<BATCH / 2, NTHR>>>(x, w_ih, w_hh, b_ih, b_hh,
                                                w_out, b_out, out);
}

// round 6
// speedup vs baseline: 5.6962x; 5.6962x over previous
#include <cuda_runtime.h>
#include <string.h>

#define BATCH 128
#define TLEN  8192
#define HDIM  96
#define NTHR  416   // 12 gate warps + 1 output warp

// Packed fp32x2 FMA (Blackwell).
#define FMA2(d, a, b, c) \
    asm("fma.rn.f32x2 %0, %1, %2, %3;" : "=l"(d) : "l"(a), "l"(b), "l"(c))
#define ADD2(d, a, b) \
    asm("add.rn.f32x2 %0, %1, %2;" : "=l"(d) : "l"(a), "l"(b))
#define UNPACK2(lo, hi, v) \
    asm("mov.b64 {%0, %1}, %2;" : "=f"(lo), "=f"(hi) : "l"(v))

__device__ __forceinline__ float ex2_fast(float x) {
    float y; asm("ex2.approx.f32 %0, %1;" : "=f"(y) : "f"(x)); return y;
}
__device__ __forceinline__ float rcp_fast(float x) {
    float y; asm("rcp.approx.f32 %0, %1;" : "=f"(y) : "f"(x)); return y;
}
__device__ __forceinline__ void cta_bar() {
    asm volatile("bar.sync 0;" ::: "memory");
}

#define LOG2E 1.4426950408889634f

// one LSTM step for a gate-warp lane: matvec quarter + butterfly + act + update
__device__ __forceinline__ void lstm_step(
    const float* __restrict__ hin, float* __restrict__ hout, float xt,
    const ulonglong2 (&wreg)[4][6], float wi, float bias, float mq,
    int base, int b0, int b1, int u, float& c)
{
    const ulonglong2* hq = (const ulonglong2*)hin;   // hin already offset by 24q
    ulonglong2 h0 = hq[0], h1 = hq[1], h2v = hq[2];
    ulonglong2 h3 = hq[3], h4 = hq[4], h5 = hq[5];
    float pre = fmaf(xt, wi, bias);

    unsigned long long acc[4][2];
    #pragma unroll
    for (int g = 0; g < 4; g++) { acc[g][0] = 0ull; acc[g][1] = 0ull; }
    #pragma unroll
    for (int g = 0; g < 4; g++) {
        FMA2(acc[g][0], wreg[g][0].x, h0.x, acc[g][0]);
        FMA2(acc[g][1], wreg[g][0].y, h0.y, acc[g][1]);
        FMA2(acc[g][0], wreg[g][1].x, h1.x, acc[g][0]);
        FMA2(acc[g][1], wreg[g][1].y, h1.y, acc[g][1]);
        FMA2(acc[g][0], wreg[g][2].x, h2v.x, acc[g][0]);
        FMA2(acc[g][1], wreg[g][2].y, h2v.y, acc[g][1]);
        FMA2(acc[g][0], wreg[g][3].x, h3.x, acc[g][0]);
        FMA2(acc[g][1], wreg[g][3].y, h3.y, acc[g][1]);
        FMA2(acc[g][0], wreg[g][4].x, h4.x, acc[g][0]);
        FMA2(acc[g][1], wreg[g][4].y, h4.y, acc[g][1]);
        FMA2(acc[g][0], wreg[g][5].x, h5.x, acc[g][0]);
        FMA2(acc[g][1], wreg[g][5].y, h5.y, acc[g][1]);
    }
    float pg[4];
    #pragma unroll
    for (int g = 0; g < 4; g++) {
        unsigned long long s;
        ADD2(s, acc[g][0], acc[g][1]);
        float lo, hi;
        UNPACK2(lo, hi, s);
        pg[g] = lo + hi;
    }

    // butterfly: lane q ends with gate q's full sum
    float keepA = b0 ? pg[1] : pg[0];
    float sendA = b0 ? pg[0] : pg[1];
    float keepB = b0 ? pg[3] : pg[2];
    float sendB = b0 ? pg[2] : pg[3];
    keepA += __shfl_xor_sync(0xffffffffu, sendA, 1);
    keepB += __shfl_xor_sync(0xffffffffu, sendB, 1);
    float keep = b1 ? keepB : keepA;
    float send = b1 ? keepA : keepB;
    float z = keep + __shfl_xor_sync(0xffffffffu, send, 2) + pre;

    // branchless activation in log2 domain: 1 - mq/(2^z + 1)
    float e   = ex2_fast(z);
    float r   = rcp_fast(e + 1.0f);
    float act = fmaf(-mq, r, 1.0f);

    // all 4 sublanes gather all 4 activations (4 parallel shfls)
    float iv = __shfl_sync(0xffffffffu, act, base);
    float fv = __shfl_sync(0xffffffffu, act, base + 1);
    float gv = __shfl_sync(0xffffffffu, act, base + 2);
    float ov = __shfl_sync(0xffffffffu, act, base + 3);

    // redundant branchless update: all 4 lanes compute identical c, h
    c = fmaf(fv, c, iv * gv);
    float e2 = ex2_fast(c * (2.0f * LOG2E));
    float hc = ov * fmaf(-2.0f, rcp_fast(e2 + 1.0f), 1.0f);
    hout[u] = hc;   // 4 lanes store the same value to the same address (benign)
}

__global__ void __launch_bounds__(NTHR, 1)
lstm_persistent_kernel(const float* __restrict__ x,
                       const float* __restrict__ w_ih,
                       const float* __restrict__ w_hh,
                       const float* __restrict__ b_ih,
                       const float* __restrict__ b_hh,
                       const float* __restrict__ w_out,
                       const float* __restrict__ b_out,
                       float* __restrict__ out)
{
    __shared__ __align__(16) float x_s[TLEN];      // 32 KB: whole input row
    __shared__ __align__(16) float h_s[2][HDIM];   // ping-pong hidden state

    const int tid  = threadIdx.x;
    const int b    = blockIdx.x;
    const int wid  = tid >> 5;
    const int lane = tid & 31;

    {   // stage whole x row, coalesced float4
        const float4* xg = (const float4*)(x + (size_t)b * TLEN);
        float4* xs = (float4*)x_s;
        for (int i = tid; i < TLEN / 4; i += NTHR) xs[i] = xg[i];
    }
    if (tid < HDIM) { h_s[0][tid] = 0.0f; h_s[1][tid] = 0.0f; }

    const bool is_gate = (wid < 12);
    const int u = 8 * wid + (lane >> 2);   // hidden unit 0..95
    const int q = lane & 3;                // h-quarter / gate id

    ulonglong2 wreg[4][6];
    float wi = 0.0f, bias = 0.0f;
    if (is_gate) {
        #pragma unroll
        for (int g = 0; g < 4; g++) {
            const float sg = (g == 2) ? 2.0f * LOG2E : LOG2E;
            const float4* wr = (const float4*)(w_hh + (size_t)(g * HDIM + u) * HDIM + 24 * q);
            #pragma unroll
            for (int j = 0; j < 6; j++) {
                float4 t = wr[j];
                t.x *= sg; t.y *= sg; t.z *= sg; t.w *= sg;
                ulonglong2 pk;
                memcpy(&pk, &t, 16);
                wreg[g][j] = pk;
            }
        }
        const float sq = (q == 2) ? 2.0f * LOG2E : LOG2E;
        const int row = q * HDIM + u;
        wi   = w_ih[row] * sq;
        bias = (b_ih[row] + b_hh[row]) * sq;
    }
    const float mq = (q == 2) ? 2.0f : 1.0f;
    const int  base = lane & ~3;
    const int  b0 = lane & 1, b1 = lane & 2;

    float* outrow = out + (size_t)b * TLEN;

    __syncthreads();   // x_s, h init, weights ready (convergent)

    if (is_gate) {
        // ---------------- gate warps: uniform loop, no per-step role branch ----
        const float* hin0 = h_s[0] + 24 * q;
        const float* hin1 = h_s[1] + 24 * q;
        float c = 0.0f;
        #pragma unroll 1
        for (int t = 0; t < TLEN; t += 2) {
            lstm_step(hin0, h_s[1], x_s[t],     wreg, wi, bias, mq, base, b0, b1, u, c);
            cta_bar();
            lstm_step(hin1, h_s[0], x_s[t + 1], wreg, wi, bias, mq, base, b0, b1, u, c);
            cta_bar();
        }
    } else {
        // ---------------- output warp: its own uniform loop -------------------
        float wo0 = w_out[lane];
        float wo1 = w_out[lane + 32];
        float wo2 = w_out[lane + 64];
        float bo  = b_out[0];

        cta_bar();   // t = 0: nothing to emit yet
        #pragma unroll 1
        for (int t = 1; t < TLEN; t++) {
            const float* hprev = h_s[t & 1];   // h(t-1)
            float part = hprev[lane] * wo0 + hprev[lane + 32] * wo1
                       + hprev[lane + 64] * wo2;
            part += __shfl_xor_sync(0xffffffffu, part, 16);
            part += __shfl_xor_sync(0xffffffffu, part, 8);
            part += __shfl_xor_sync(0xffffffffu, part, 4);
            part += __shfl_xor_sync(0xffffffffu, part, 2);
            part += __shfl_xor_sync(0xffffffffu, part, 1);
            if (lane == 0) outrow[t - 1] = part + bo;
            cta_bar();
        }
        // final y(T-1): h(T-1) lives in h_s[0] (TLEN even)
        const float* hlast = h_s[0];
        float part = hlast[lane] * wo0 + hlast[lane + 32] * wo1
                   + hlast[lane + 64] * wo2;
        part += __shfl_xor_sync(0xffffffffu, part, 16);
        part += __shfl_xor_sync(0xffffffffu, part, 8);
        part += __shfl_xor_sync(0xffffffffu, part, 4);
        part += __shfl_xor_sync(0xffffffffu, part, 2);
        part += __shfl_xor_sync(0xffffffffu, part, 1);
        if (lane == 0) outrow[TLEN - 1] = part + bo;
    }
}

extern "C" void kernel_launch(void* const* d_in, const int* in_sizes, int n_in,
                              void* d_out, int out_size)
{
    const float* x     = (const float*)d_in[0];
    const float* w_ih  = (const float*)d_in[1];
    const float* w_hh  = (const float*)d_in[2];
    const float* b_ih  = (const float*)d_in[3];
    const float* b_hh  = (const float*)d_in[4];
    const float* w_out = (const float*)d_in[5];
    const float* b_out = (const float*)d_in[6];
    float* out = (float*)d_out;

    lstm_persistent_kernel<<<BATCH, NTHR>>>(x, w_ih, w_hh, b_ih, b_hh,
                                            w_out, b_out, out);
}